// round 7
// baseline (speedup 1.0000x reference)
#include <cuda_runtime.h>
#include <math.h>

#define HWSZ   9216
#define GH     96
#define GW     96
#define NPAIR  16                  // 8 samples x 2 directions
#define BANDS  8
#define RPB    (GH / BANDS)        // 12 rows per band
#define BPX    (RPB * GW)          // 1152 pixels per band
#define NT     384
#define NBLK   (NPAIR * BANDS)     // 128 blocks, one per SM (wave 1)

__device__ int      g_pairmax[NPAIR] = {-1,-1,-1,-1,-1,-1,-1,-1,
                                        -1,-1,-1,-1,-1,-1,-1,-1};
__device__ int      g_tcnt[NPAIR];        // written by band-0 block each run
__device__ unsigned g_c2 = 0;             // completion counter (self-resetting)

// pair = 2*sample + dir;  dir 0: src = A&~B, tgt = B;  dir 1: src = ~A&B, tgt = A.
// Each block redundantly computes the FULL row-distance^2 tile for its pair in
// local smem (no inter-block barrier), then ring-searches only its band.
__global__ __launch_bounds__(NT) void hausdorff_kernel(
    const float* __restrict__ predict,
    const float* __restrict__ target,
    float* __restrict__ out)
{
    const int pair = blockIdx.x >> 3;
    const int band = blockIdx.x & 7;
    const int dir  = pair & 1;
    const int tid  = threadIdx.x;
    const int base = band * BPX;

    __shared__ unsigned char  s_nib[HWSZ / 4];      // 2304 B: tgt nibble | src nibble<<4
    __shared__ unsigned       s_tgtpad[GH * 8];     // 8 words/row: [0,0,w0,w1,w2,0,0,0]
    __shared__ unsigned       s_srcbits[BPX / 32];  // own band only, 36 words
    __shared__ unsigned short s_rd2[HWSZ];          // full-tile rd2 (18 KB)
    __shared__ int            s_warpmax[NT / 32];
    __shared__ int            s_tcnt;

    // zero the 5 pad words per row; init tgt counter
    if (tid < GH * 5) {
        int r = tid / 5, pi = tid % 5;
        s_tgtpad[r * 8 + ((pi < 2) ? pi : pi + 3)] = 0u;
    }
    if (tid == 0) s_tcnt = 0;

    const float4* pa4 = (const float4*)(predict + (pair >> 1) * HWSZ);
    const float4* pb4 = (const float4*)(target  + (pair >> 1) * HWSZ);

    // ---- Phase 1a: vector loads -> per-4px nibbles (rintf(x)>0.5 <=> x>0.5) ----
    #pragma unroll
    for (int k = 0; k < HWSZ / 4 / NT; k++) {       // 6 iterations
        const int q = tid + k * NT;                 // float4 index = px/4
        float4 va = pa4[q], vb = pb4[q];
        unsigned an = (unsigned)(va.x > 0.5f) | ((unsigned)(va.y > 0.5f) << 1)
                    | ((unsigned)(va.z > 0.5f) << 2) | ((unsigned)(va.w > 0.5f) << 3);
        unsigned bn = (unsigned)(vb.x > 0.5f) | ((unsigned)(vb.y > 0.5f) << 1)
                    | ((unsigned)(vb.z > 0.5f) << 2) | ((unsigned)(vb.w > 0.5f) << 3);
        unsigned tn = dir ? an : bn;
        unsigned sn = dir ? (bn & ~an) : (an & ~bn);
        s_nib[q] = (unsigned char)(tn | (sn << 4));
    }
    __syncthreads();

    // ---- Phase 1b: compress 8 nibble-bytes -> one 32-bit row-mask word ----
    if (tid < GH * 3) {                             // 288 words
        const int li = tid / 3, wi = tid - li * 3;
        unsigned long long x = *(const unsigned long long*)(s_nib + li * 24 + wi * 8);
        unsigned long long yt = x & 0x0F0F0F0F0F0F0F0Full;
        unsigned long long ys = (x >> 4) & 0x0F0F0F0F0F0F0F0Full;
        yt = (yt | (yt >> 4))  & 0x00FF00FF00FF00FFull;
        ys = (ys | (ys >> 4))  & 0x00FF00FF00FF00FFull;
        yt = (yt | (yt >> 8))  & 0x0000FFFF0000FFFFull;
        ys = (ys | (ys >> 8))  & 0x0000FFFF0000FFFFull;
        unsigned tw = (unsigned)(yt | (yt >> 16));
        unsigned sw = (unsigned)(ys | (ys >> 16));
        s_tgtpad[li * 8 + 2 + wi] = tw;
        const int lr = li - band * RPB;             // row within own band?
        if (lr >= 0 && lr < RPB) s_srcbits[lr * 3 + wi] = sw;
        int wsum = __reduce_add_sync(0xffffffffu, __popc(tw));
        if ((tid & 31) == 0) atomicAdd(&s_tcnt, wsum);
    }
    __syncthreads();

    // ---- Phase 2: full-tile 1D row distance^2 (24 px/thread) -> local smem ----
    #pragma unroll 6
    for (int k = 0; k < HWSZ / NT; k++) {           // 24 iterations
        const int p  = tid + k * NT;
        const int li = p / GW;
        const int j  = p - li * GW;
        const int w  = j >> 5, off = j & 31;
        const unsigned* bw = s_tgtpad + li * 8 + 2 + w;   // padded: bw[-2..2] valid
        unsigned d2v = bw[-2], d1v = bw[-1], m = bw[0], u1v = bw[1], u2v = bw[2];
        unsigned hi = 0xffffffffu << off;
        unsigned lo = (2u << off) - 1u;             // off=31 wraps to ~0

        unsigned long long upair = (unsigned long long)(m & hi)
                                 | ((unsigned long long)u1v << 32);
        unsigned long long dpair = (unsigned long long)d1v
                                 | ((unsigned long long)(m & lo) << 32);

        int up = upair ? (w * 32 + __ffsll(upair) - 1 - j)
               : (u2v  ? (w * 32 + 64 + __ffs(u2v) - 1 - j) : 1000);
        int dn = dpair ? (j - (w * 32 - 32 + 63 - __clzll(dpair)))
               : (d2v  ? (j - (w * 32 - 64 + 31 - __clz(d2v))) : 1000);
        int d = min(min(up, dn), 255);              // empty-row sentinel (255^2 fits u16)
        s_rd2[p] = (unsigned short)(d * d);
    }
    __syncthreads();

    // ---- Phase 3: exact early-exit ring search (columns), own band src px ----
    int maxd2 = -1;
    #pragma unroll
    for (int k = 0; k < BPX / NT; k++) {            // 3 iterations
        const int lp = tid + k * NT;
        if ((s_srcbits[lp >> 5] >> (lp & 31)) & 1u) {
            const int p = base + lp;
            const int i = p / GW;
            int best = (int)s_rd2[p];
            for (int r = 1; r < GH && r * r < best; r++) {
                int rr = r * r;
                if (i >= r)      best = min(best, rr + (int)s_rd2[p - r * GW]);
                if (i + r < GH)  best = min(best, rr + (int)s_rd2[p + r * GW]);
            }
            maxd2 = max(maxd2, best);
        }
    }

    // ---- Phase 4: block reduce -> per-pair atomicMax -> last-block finalize ----
    #pragma unroll
    for (int off = 16; off > 0; off >>= 1)
        maxd2 = max(maxd2, __shfl_xor_sync(0xffffffffu, maxd2, off));
    if ((tid & 31) == 0) s_warpmax[tid >> 5] = maxd2;
    __syncthreads();

    if (tid == 0) {
        int m = -1;
        #pragma unroll
        for (int w = 0; w < NT / 32; w++) m = max(m, s_warpmax[w]);
        if (m >= 0) atomicMax(&g_pairmax[pair], m);
        if (band == 0) g_tcnt[pair] = s_tcnt;       // non-redundant publish

        __threadfence();                            // release max/tcnt writes
        unsigned done = atomicAdd(&g_c2, 1u);
        if (done == NBLK - 1) {                     // last block finalizes
            __threadfence();                        // acquire all blocks' writes
            int pm[NPAIR], tc[NPAIR];
            #pragma unroll
            for (int q = 0; q < NPAIR; q++) {       // batched independent L2 loads
                pm[q] = __ldcg(&g_pairmax[q]);
                tc[q] = __ldcg(&g_tcnt[q]);
            }
            float s = 0.0f;
            #pragma unroll
            for (int q = 0; q < 8; q++) {
                float v0 = (pm[2*q]   < 0) ? 0.0f : ((tc[2*q]   == 0) ? 1e9f : sqrtf((float)pm[2*q])   * (1.0f/96.0f));
                float v1 = (pm[2*q+1] < 0) ? 0.0f : ((tc[2*q+1] == 0) ? 1e9f : sqrtf((float)pm[2*q+1]) * (1.0f/96.0f));
                s += fmaxf(v0, v1);
            }
            out[0] = s * 0.125f;
            // reset control state for the next graph replay
            #pragma unroll
            for (int q = 0; q < NPAIR; q++) g_pairmax[q] = -1;
            g_c2 = 0;
            __threadfence();
        }
    }
}

extern "C" void kernel_launch(void* const* d_in, const int* in_sizes, int n_in,
                              void* d_out, int out_size)
{
    const float* predict = (const float*)d_in[0];
    const float* target  = (const float*)d_in[1];
    hausdorff_kernel<<<NBLK, NT>>>(predict, target, (float*)d_out);
}

// round 8
// speedup vs baseline: 1.7725x; 1.7725x over previous
#include <cuda_runtime.h>
#include <math.h>

#define HWSZ   9216
#define GH     96
#define GW     96
#define NPAIR  16                  // 8 samples x 2 directions
#define BANDS  8
#define RPB    (GH / BANDS)        // 12 rows per band
#define BPX    (RPB * GW)          // 1152 pixels per band
#define NT     384
#define PPT    (BPX / NT)          // 3 pixels per thread, exact
#define NBLK   (NPAIR * BANDS)     // 128 blocks

// global scratch (per-pair 1D row distance, u8) + control state
__device__ unsigned char g_rd[NPAIR][HWSZ];
__device__ int      g_pairmax[NPAIR] = {-1,-1,-1,-1,-1,-1,-1,-1,
                                        -1,-1,-1,-1,-1,-1,-1,-1};
__device__ int      g_tcnt[NPAIR];        // zero-init
__device__ unsigned g_c1[NPAIR];          // per-pair band barrier, zero-init
__device__ unsigned g_c2 = 0;             // global completion counter

// pair = 2*sample + dir.
//   dir 0: src = A & ~B, tgt = B   (distA)
//   dir 1: src = ~A & B, tgt = A   (distB)
__global__ __launch_bounds__(NT) void hausdorff_kernel(
    const float* __restrict__ predict,
    const float* __restrict__ target,
    float* __restrict__ out)
{
    const int pair = blockIdx.x >> 3;
    const int band = blockIdx.x & 7;
    const int dir  = pair & 1;
    const int tid  = threadIdx.x;
    const int base = band * BPX;           // absolute pixel base of this band

    // padded row-bit layout: 8 words/row = [0,0, w0,w1,w2, 0,0,0]; row base = i*8+2
    __shared__ unsigned       s_tgtpad[RPB * 8];    // 96 words
    __shared__ unsigned       s_srcbits[BPX / 32];  // 36 words
    __shared__ unsigned char  s_rd[HWSZ];           // full-tile 1D row distance (9 KB)
    __shared__ int            s_warpmax[NT / 32];

    const float* pa = predict + (pair >> 1) * HWSZ;
    const float* pb = target  + (pair >> 1) * HWSZ;

    // ---- prefetch input scalars first: start the LDG wave before any setup ----
    float va[PPT], vb[PPT];
    #pragma unroll
    for (int k = 0; k < PPT; k++) {
        const int p = base + tid + k * NT;
        va[k] = pa[p];
        vb[k] = pb[p];
    }

    // zero the 5 pad words per row (disjoint from ballot-written data words)
    if (tid < RPB * 5) {
        int r = tid / 5, pi = tid % 5;
        s_tgtpad[r * 8 + ((pi < 2) ? pi : pi + 3)] = 0u;
    }

    // ---- Phase 1: masks for this band (rintf(x)>0.5 <=> x>0.5, half-even) ----
    int tcount = 0;
    #pragma unroll
    for (int k = 0; k < PPT; k++) {
        const int lp = tid + k * NT;       // 0..1151, lane0 word-aligned
        bool a = va[k] > 0.5f;
        bool b = vb[k] > 0.5f;
        bool t = dir ? a : b;
        bool s = dir ? ((!a) && b) : (a && (!b));
        unsigned tb = __ballot_sync(0xffffffffu, t);
        unsigned sb = __ballot_sync(0xffffffffu, s);
        if ((tid & 31) == 0) {
            const int ww = lp >> 5;        // 0..35
            const int li = ww / 3, wi = ww - li * 3;
            s_tgtpad[li * 8 + 2 + wi] = tb;
            s_srcbits[ww] = sb;
            tcount += __popc(tb);
        }
    }
    if ((tid & 31) == 0 && tcount) atomicAdd(&g_tcnt[pair], tcount);
    __syncthreads();

    // ---- Phase 2: 1D row distance via padded-row indexed loads + 64-bit scans ----
    #pragma unroll
    for (int k = 0; k < PPT; k++) {
        const int lp = tid + k * NT;
        const int li = lp / GW;
        const int j  = lp - li * GW;
        const int w  = j >> 5, off = j & 31;
        const unsigned* bw = s_tgtpad + li * 8 + 2 + w;   // padded: bw[-2..2] valid
        unsigned d2v = bw[-2], d1v = bw[-1], m = bw[0], u1v = bw[1], u2v = bw[2];
        unsigned hi = 0xffffffffu << off;
        unsigned lo = (2u << off) - 1u;     // off=31 wraps to ~0

        unsigned long long upair = (unsigned long long)(m & hi)
                                 | ((unsigned long long)u1v << 32);
        unsigned long long dpair = (unsigned long long)d1v
                                 | ((unsigned long long)(m & lo) << 32);

        int up = upair ? (w * 32 + __ffsll(upair) - 1 - j)
               : (u2v  ? (w * 32 + 64 + __ffs(u2v) - 1 - j) : 1000);
        int dn = dpair ? (j - (w * 32 - 32 + 63 - __clzll(dpair)))
               : (d2v  ? (j - (w * 32 - 64 + 31 - __clz(d2v))) : 1000);
        int d = min(min(up, dn), 255);              // empty-row sentinel
        g_rd[pair][base + lp] = (unsigned char)d;   // u8 exchange (d <= 95 or 255)
    }

    // ---- per-pair barrier: all 8 bands' rd visible ----
    __syncthreads();
    if (tid == 0) {
        __threadfence();                            // release rd writes
        atomicAdd(&g_c1[pair], 1u);
        volatile unsigned* c = &g_c1[pair];
        while (*c < BANDS) { }
        __threadfence();                            // acquire
    }
    __syncthreads();

    // ---- Phase 3a: pull full 9KB rd tile L2 -> smem, 64-bit loads ----
    {
        const uint2* gsrc = (const uint2*)&g_rd[pair][0];   // 1152 uint2
        uint2* sdst = (uint2*)s_rd;
        #pragma unroll
        for (int k = 0; k < 3; k++)
            sdst[tid + k * NT] = __ldcg(gsrc + tid + k * NT);
    }
    __syncthreads();

    // ---- Phase 3b: exact early-exit ring search (columns), src px only ----
    int maxd2 = -1;
    #pragma unroll
    for (int k = 0; k < PPT; k++) {
        const int lp = tid + k * NT;
        if ((s_srcbits[lp >> 5] >> (lp & 31)) & 1u) {
            const int p = base + lp;
            const int i = p / GW;                   // absolute row
            int d0 = (int)s_rd[p];
            int best = d0 * d0;                     // sentinel 255^2 > any true d2
            for (int r = 1; r < GH && r * r < best; r++) {
                int rr = r * r;
                if (i >= r) {
                    int du = (int)s_rd[p - r * GW];
                    best = min(best, rr + du * du);
                }
                if (i + r < GH) {
                    int dd = (int)s_rd[p + r * GW];
                    best = min(best, rr + dd * dd);
                }
            }
            maxd2 = max(maxd2, best);
        }
    }

    // ---- Phase 4: block reduce -> per-pair atomicMax -> last-block finalize ----
    #pragma unroll
    for (int off = 16; off > 0; off >>= 1)
        maxd2 = max(maxd2, __shfl_xor_sync(0xffffffffu, maxd2, off));
    if ((tid & 31) == 0) s_warpmax[tid >> 5] = maxd2;
    __syncthreads();

    if (tid == 0) {
        int m = -1;
        #pragma unroll
        for (int w = 0; w < NT / 32; w++) m = max(m, s_warpmax[w]);
        if (m >= 0) atomicMax(&g_pairmax[pair], m);

        __threadfence();
        unsigned done = atomicAdd(&g_c2, 1u);
        if (done == NBLK - 1) {                     // last block finalizes
            __threadfence();
            // batched, independent L2 loads (MLP-covered)
            int pm[NPAIR], tc[NPAIR];
            #pragma unroll
            for (int q = 0; q < NPAIR; q++) {
                pm[q] = __ldcg(&g_pairmax[q]);
                tc[q] = __ldcg(&g_tcnt[q]);
            }
            float s = 0.0f;
            #pragma unroll
            for (int q = 0; q < 8; q++) {
                float v0 = (pm[2*q]   < 0) ? 0.0f : ((tc[2*q]   == 0) ? 1e9f : sqrtf((float)pm[2*q])   * (1.0f/96.0f));
                float v1 = (pm[2*q+1] < 0) ? 0.0f : ((tc[2*q+1] == 0) ? 1e9f : sqrtf((float)pm[2*q+1]) * (1.0f/96.0f));
                s += fmaxf(v0, v1);
            }
            out[0] = s * 0.125f;
            // reset all control state for the next graph replay
            #pragma unroll
            for (int q = 0; q < NPAIR; q++) {
                g_pairmax[q] = -1;
                g_tcnt[q]    = 0;
                g_c1[q]      = 0;
            }
            g_c2 = 0;
            __threadfence();
        }
    }
}

extern "C" void kernel_launch(void* const* d_in, const int* in_sizes, int n_in,
                              void* d_out, int out_size)
{
    const float* predict = (const float*)d_in[0];
    const float* target  = (const float*)d_in[1];
    hausdorff_kernel<<<NBLK, NT>>>(predict, target, (float*)d_out);
}